// round 3
// baseline (speedup 1.0000x reference)
#include <cuda_runtime.h>
#include <cstdint>

#define NN 100000
#define HH 128
#define GG 64
#define EIN 32

// ---------------- static device scratch (no allocations allowed) ------------
// __align__(16): accessed as float4 / red.v4.f32.
__device__ __align__(16) float d_S1[(size_t)NN * HH];   // agg / a1 scratch
__device__ __align__(16) float d_S2[(size_t)NN * HH];   // h0 / h2
__device__ __align__(16) float d_S3[(size_t)NN * HH];   // h1 / a2
__device__ __align__(16) float d_cnt[NN];
__device__ __align__(16) float d_invc[NN];
__device__ __align__(16) float d_d13[(size_t)NN * 2];
__device__ __align__(16) float d_g[GG * 4];

// ---------------- helpers ---------------------------------------------------
__device__ __forceinline__ void red4(float* p, float4 v) {
    asm volatile("red.global.add.v4.f32 [%0], {%1,%2,%3,%4};"
                 :: "l"(p), "f"(v.x), "f"(v.y), "f"(v.z), "f"(v.w) : "memory");
}

// ---------------- zero -------------------------------------------------------
__global__ void zero_k(float4* __restrict__ p, int n4) {
    int stride = gridDim.x * blockDim.x;
    for (int i = blockIdx.x * blockDim.x + threadIdx.x; i < n4; i += stride)
        p[i] = make_float4(0.f, 0.f, 0.f, 0.f);
}

// ---------------- edge aggregation: layer0 (32-dim), thread per edge --------
__global__ void edge_agg32(const float* __restrict__ x,
                           const int* __restrict__ src,
                           const int* __restrict__ dst,
                           float* __restrict__ agg, float* __restrict__ cnt, int E) {
    int e = blockIdx.x * blockDim.x + threadIdx.x;
    if (e >= E) return;
    int s = src[e];
    int d = dst[e];
    const float4* xs = (const float4*)(x + (size_t)s * EIN);
    float* ap = agg + (size_t)d * EIN;
#pragma unroll
    for (int j = 0; j < 8; j++) {
        float4 v = xs[j];
        red4(ap + j * 4, v);
    }
    atomicAdd(cnt + d, 1.0f);
}

// ---------------- edge aggregation: 128-dim, warp per edge ------------------
__global__ void edge_agg128(const float* __restrict__ h,
                            const int* __restrict__ src,
                            const int* __restrict__ dst,
                            float* __restrict__ agg, int E) {
    int gt = blockIdx.x * blockDim.x + threadIdx.x;
    int e = gt >> 5;
    int lane = gt & 31;
    if (e >= E) return;
    int s = 0, d = 0;
    if (lane == 0) { s = src[e]; d = dst[e]; }
    s = __shfl_sync(0xffffffffu, s, 0);
    d = __shfl_sync(0xffffffffu, d, 0);
    float4 v = ((const float4*)(h + (size_t)s * HH))[lane];
    red4(agg + (size_t)d * HH + lane * 4, v);
}

// ---------------- inverse counts --------------------------------------------
__global__ void invc_k(const float* __restrict__ cnt, float* __restrict__ invc, int n) {
    int i = blockIdx.x * blockDim.x + threadIdx.x;
    if (i < n) invc[i] = 1.0f / fmaxf(cnt[i], 1.0f);
}

// ---------------- fused SAGE GEMM: out = relu([agg*invc | x] @ [Wl;Wr] + b) -
// KA = agg feature dim, KB = x feature dim (0 => plain GEMM, no divide)
template <int KA, int KB, bool DIV>
__global__ void __launch_bounds__(256)
sage_gemm(const float* __restrict__ Aagg, const float* __restrict__ Ax,
          const float* __restrict__ invc,
          const float* __restrict__ Wl, const float* __restrict__ Wr,
          const float* __restrict__ bias, float* __restrict__ out, int n) {
    constexpr int K = KA + KB;
    constexpr int BM = 128, BN = 128, BK = 8;
    __shared__ float As[BK][BM + 4];
    __shared__ float Ws[BK][BN];
    int tid = threadIdx.x;
    int row0 = blockIdx.x * BM;

    int arow = tid >> 1;
    int acol = (tid & 1) * 4;
    int grow = row0 + arow;
    bool rvalid = grow < n;
    float scale = 1.0f;
    if (DIV && rvalid) scale = invc[grow];

    int wk = tid >> 5;
    int wcol = (tid & 31) * 4;

    int tx = tid & 15, ty = tid >> 4;
    float acc[8][8];
#pragma unroll
    for (int m = 0; m < 8; m++)
#pragma unroll
        for (int q = 0; q < 8; q++) acc[m][q] = 0.f;

    for (int k0 = 0; k0 < K; k0 += BK) {
        float4 av = make_float4(0.f, 0.f, 0.f, 0.f);
        int kg = k0 + acol;
        if (rvalid) {
            if (KB == 0 || kg < KA) {
                av = *(const float4*)(Aagg + (size_t)grow * KA + kg);
                av.x *= scale; av.y *= scale; av.z *= scale; av.w *= scale;
            } else {
                av = *(const float4*)(Ax + (size_t)grow * KB + (kg - KA));
            }
        }
        As[acol + 0][arow] = av.x;
        As[acol + 1][arow] = av.y;
        As[acol + 2][arow] = av.z;
        As[acol + 3][arow] = av.w;

        int kw = k0 + wk;
        float4 wv;
        if (KB == 0 || kw < KA) wv = *(const float4*)(Wl + (size_t)kw * BN + wcol);
        else                    wv = *(const float4*)(Wr + (size_t)(kw - KA) * BN + wcol);
        *(float4*)&Ws[wk][wcol] = wv;

        __syncthreads();
#pragma unroll
        for (int kk = 0; kk < BK; kk++) {
            float a[8], b[8];
#pragma unroll
            for (int m = 0; m < 8; m++) a[m] = As[kk][ty * 8 + m];
#pragma unroll
            for (int q = 0; q < 8; q++) b[q] = Ws[kk][tx * 8 + q];
#pragma unroll
            for (int m = 0; m < 8; m++)
#pragma unroll
                for (int q = 0; q < 8; q++) acc[m][q] += a[m] * b[q];
        }
        __syncthreads();
    }

    float bv[8];
#pragma unroll
    for (int q = 0; q < 8; q++) bv[q] = bias[tx * 8 + q];
#pragma unroll
    for (int m = 0; m < 8; m++) {
        int r = row0 + ty * 8 + m;
        if (r < n) {
#pragma unroll
            for (int q = 0; q < 8; q += 4) {
                float4 v;
                v.x = fmaxf(acc[m][q + 0] + bv[q + 0], 0.f);
                v.y = fmaxf(acc[m][q + 1] + bv[q + 1], 0.f);
                v.z = fmaxf(acc[m][q + 2] + bv[q + 2], 0.f);
                v.w = fmaxf(acc[m][q + 3] + bv[q + 3], 0.f);
                *(float4*)(out + (size_t)r * BN + tx * 8 + q) = v;
            }
        }
    }
}

// ---------------- fc head + aux layer1: warp per node -----------------------
__global__ void fc_a1_k(const float* __restrict__ h2,
                        const float* __restrict__ Wfc, const float* __restrict__ bfc,
                        const float* __restrict__ Wa1, const float* __restrict__ ba1,
                        float* __restrict__ d13, float* __restrict__ a1out, int n) {
    int gt = blockIdx.x * blockDim.x + threadIdx.x;
    int i = gt >> 5;
    int lane = gt & 31;
    if (i >= n) return;
    float4 h = ((const float4*)(h2 + (size_t)i * HH))[lane];
    int k = lane * 4;
    float s1 = h.x * Wfc[(k + 0) * 3 + 0] + h.y * Wfc[(k + 1) * 3 + 0]
             + h.z * Wfc[(k + 2) * 3 + 0] + h.w * Wfc[(k + 3) * 3 + 0];
    float s3 = h.x * Wfc[(k + 0) * 3 + 2] + h.y * Wfc[(k + 1) * 3 + 2]
             + h.z * Wfc[(k + 2) * 3 + 2] + h.w * Wfc[(k + 3) * 3 + 2];
#pragma unroll
    for (int off = 16; off > 0; off >>= 1) {
        s1 += __shfl_down_sync(0xffffffffu, s1, off);
        s3 += __shfl_down_sync(0xffffffffu, s3, off);
    }
    float d1 = __shfl_sync(0xffffffffu, s1, 0) + bfc[0];
    float d3 = __shfl_sync(0xffffffffu, s3, 0) + bfc[2];
    if (lane == 0) {
        d13[(size_t)i * 2 + 0] = d1;
        d13[(size_t)i * 2 + 1] = d3;
    }
    float4 w0 = *(const float4*)(Wa1 + k);
    float4 w1 = *(const float4*)(Wa1 + HH + k);
    float4 b  = *(const float4*)(ba1 + k);
    float4 o;
    o.x = fmaxf(d1 * w0.x + d3 * w1.x + b.x, 0.f);
    o.y = fmaxf(d1 * w0.y + d3 * w1.y + b.y, 0.f);
    o.z = fmaxf(d1 * w0.z + d3 * w1.z + b.z, 0.f);
    o.w = fmaxf(d1 * w0.w + d3 * w1.w + b.w, 0.f);
    *(float4*)(a1out + (size_t)i * HH + k) = o;
}

// ---------------- aux output + group accumulation: warp per node ------------
__global__ void final_k(const float* __restrict__ a2,
                        const float* __restrict__ Wao, const float* __restrict__ bao,
                        const float* __restrict__ d13,
                        const int* __restrict__ batch,
                        float* __restrict__ g, int n) {
    __shared__ float sg[GG * 4];
    int tid = threadIdx.x;
    for (int j = tid; j < GG * 4; j += blockDim.x) sg[j] = 0.f;
    __syncthreads();

    int gt = blockIdx.x * blockDim.x + tid;
    int i = gt >> 5;
    int lane = gt & 31;
    if (i < n) {
        float4 v = ((const float4*)(a2 + (size_t)i * HH))[lane];
        float4 w = ((const float4*)Wao)[lane];
        float s = v.x * w.x + v.y * w.y + v.z * w.z + v.w * w.w;
#pragma unroll
        for (int off = 16; off > 0; off >>= 1)
            s += __shfl_down_sync(0xffffffffu, s, off);
        if (lane == 0) {
            float aux = s + bao[0];
            int b = batch[i];
            atomicAdd(&sg[b * 4 + 0], d13[(size_t)i * 2 + 0]);
            atomicAdd(&sg[b * 4 + 1], aux);
            atomicAdd(&sg[b * 4 + 2], d13[(size_t)i * 2 + 1]);
            atomicAdd(&sg[b * 4 + 3], 1.0f);
        }
    }
    __syncthreads();
    for (int j = tid; j < GG * 4; j += blockDim.x)
        if (sg[j] != 0.f) atomicAdd(&g[j], sg[j]);
}

// ---------------- finalize: group mean --------------------------------------
__global__ void finalize_k(const float* __restrict__ g, float* __restrict__ out) {
    int t = blockIdx.x * blockDim.x + threadIdx.x;
    if (t < GG * 3) {
        int grp = t / 3, c = t % 3;
        out[t] = g[grp * 4 + c] / fmaxf(g[grp * 4 + 3], 1.0f);
    }
}

// ---------------- launch -----------------------------------------------------
extern "C" void kernel_launch(void* const* d_in, const int* in_sizes, int n_in,
                              void* d_out, int out_size) {
    const float* x   = (const float*)d_in[0];
    const int*   ei  = (const int*)d_in[1];   // int32! (JAX x64 disabled)
    const int*   bat = (const int*)d_in[2];   // int32!
    const float* Wl0 = (const float*)d_in[3];
    const float* bl0 = (const float*)d_in[4];
    const float* Wr0 = (const float*)d_in[5];
    const float* Wl1 = (const float*)d_in[6];
    const float* bl1 = (const float*)d_in[7];
    const float* Wr1 = (const float*)d_in[8];
    const float* Wl2 = (const float*)d_in[9];
    const float* bl2 = (const float*)d_in[10];
    const float* Wr2 = (const float*)d_in[11];
    const float* Wfc = (const float*)d_in[12];
    const float* bfc = (const float*)d_in[13];
    const float* Wa1 = (const float*)d_in[14];
    const float* ba1 = (const float*)d_in[15];
    const float* Wa2 = (const float*)d_in[16];
    const float* ba2 = (const float*)d_in[17];
    const float* Wao = (const float*)d_in[18];
    const float* bao = (const float*)d_in[19];
    float* out = (float*)d_out;

    int N = in_sizes[0] / EIN;
    int E = in_sizes[1] / 2;
    const int* src = ei;
    const int* dst = ei + E;

    void* p;
    cudaGetSymbolAddress(&p, d_S1);   float* S1   = (float*)p;
    cudaGetSymbolAddress(&p, d_S2);   float* S2   = (float*)p;
    cudaGetSymbolAddress(&p, d_S3);   float* S3   = (float*)p;
    cudaGetSymbolAddress(&p, d_cnt);  float* cnt  = (float*)p;
    cudaGetSymbolAddress(&p, d_invc); float* invc = (float*)p;
    cudaGetSymbolAddress(&p, d_d13);  float* d13  = (float*)p;
    cudaGetSymbolAddress(&p, d_g);    float* g    = (float*)p;

    auto zblocks = [](int n4) { int b = (n4 + 255) / 256; return b > 8192 ? 8192 : b; };

    // --- zero agg(32-dim region), cnt, group accumulators ---
    zero_k<<<zblocks(N * EIN / 4), 256>>>((float4*)S1, N * EIN / 4);
    zero_k<<<zblocks(N / 4), 256>>>((float4*)cnt, N / 4);
    zero_k<<<1, 64>>>((float4*)g, GG);

    // --- layer 0 ---
    edge_agg32<<<(E + 255) / 256, 256>>>(x, src, dst, S1, cnt, E);
    invc_k<<<(N + 255) / 256, 256>>>(cnt, invc, N);
    int gblk = (N + 127) / 128;
    sage_gemm<EIN, EIN, true><<<gblk, 256>>>(S1, x, invc, Wl0, Wr0, bl0, S2, N);

    // --- layer 1 ---
    zero_k<<<zblocks(N * HH / 4), 256>>>((float4*)S1, N * HH / 4);
    edge_agg128<<<((size_t)E * 32 + 255) / 256, 256>>>(S2, src, dst, S1, E);
    sage_gemm<HH, HH, true><<<gblk, 256>>>(S1, S2, invc, Wl1, Wr1, bl1, S3, N);

    // --- layer 2 ---
    zero_k<<<zblocks(N * HH / 4), 256>>>((float4*)S1, N * HH / 4);
    edge_agg128<<<((size_t)E * 32 + 255) / 256, 256>>>(S3, src, dst, S1, E);
    sage_gemm<HH, HH, true><<<gblk, 256>>>(S1, S3, invc, Wl2, Wr2, bl2, S2, N);

    // --- heads ---
    fc_a1_k<<<((size_t)N * 32 + 255) / 256, 256>>>(S2, Wfc, bfc, Wa1, ba1, d13, S1, N);
    sage_gemm<HH, 0, false><<<gblk, 256>>>(S1, nullptr, nullptr, Wa2, nullptr, ba2, S3, N);
    final_k<<<((size_t)N * 32 + 255) / 256, 256>>>(S3, Wao, bao, d13, bat, g, N);
    finalize_k<<<1, 256>>>(g, out);
}

// round 4
// speedup vs baseline: 1.4364x; 1.4364x over previous
#include <cuda_runtime.h>
#include <cstdint>

#define NN 100000
#define EE 1600000
#define HH 128
#define GG 64
#define EIN 32

// ---------------- static device scratch -------------------------------------
__device__ __align__(16) float d_S1[(size_t)NN * HH];   // mean / a1 scratch
__device__ __align__(16) float d_S2[(size_t)NN * HH];   // h0 / h2
__device__ __align__(16) float d_S3[(size_t)NN * HH];   // h1 / a2
__device__ __align__(16) float d_d13[(size_t)NN * 2];
__device__ __align__(16) float d_g[GG * 4];
__device__ int d_deg[NN];
__device__ int d_rowptr[NN + 1];
__device__ int d_cursor[NN];
__device__ int d_adj[EE];
__device__ int d_blksum[256];

// ---------------- CSR build --------------------------------------------------
__global__ void zero_deg_g(int* __restrict__ deg, float* __restrict__ g, int n) {
    int i = blockIdx.x * blockDim.x + threadIdx.x;
    if (i < n) deg[i] = 0;
    if (i < GG * 4) g[i] = 0.f;
}

__global__ void hist_k(const int* __restrict__ dst, int* __restrict__ deg, int E) {
    int e = blockIdx.x * blockDim.x + threadIdx.x;
    if (e < E) atomicAdd(&deg[dst[e]], 1);
}

// block-wise exclusive scan (1024 elems/block)
__global__ void scan1_k(const int* __restrict__ deg, int* __restrict__ excl,
                        int* __restrict__ blksum, int n) {
    __shared__ int sh[1024];
    int tid = threadIdx.x;
    int i = blockIdx.x * 1024 + tid;
    int v = (i < n) ? deg[i] : 0;
    sh[tid] = v;
    __syncthreads();
#pragma unroll
    for (int off = 1; off < 1024; off <<= 1) {
        int t = (tid >= off) ? sh[tid - off] : 0;
        __syncthreads();
        sh[tid] += t;
        __syncthreads();
    }
    if (i < n) excl[i] = sh[tid] - v;
    if (tid == 1023) blksum[blockIdx.x] = sh[1023];
}

__global__ void scan2_k(int* __restrict__ blksum, int nb) {
    if (threadIdx.x == 0) {
        int run = 0;
        for (int b = 0; b < nb; b++) { int t = blksum[b]; blksum[b] = run; run += t; }
    }
}

__global__ void scan3_k(int* __restrict__ rowptr, const int* __restrict__ blksum,
                        int* __restrict__ cursor, int n, int E) {
    int i = blockIdx.x * blockDim.x + threadIdx.x;
    if (i < n) {
        int r = rowptr[i] + blksum[i >> 10];
        rowptr[i] = r;
        cursor[i] = r;
    }
    if (i == 0) rowptr[n] = E;
}

__global__ void fill_k(const int* __restrict__ src, const int* __restrict__ dst,
                       int* __restrict__ cursor, int* __restrict__ adj, int E) {
    int e = blockIdx.x * blockDim.x + threadIdx.x;
    if (e < E) {
        int slot = atomicAdd(&cursor[dst[e]], 1);
        adj[slot] = src[e];
    }
}

// ---------------- mean gather: 32-dim (layer 0), warp per node --------------
__global__ void gather32_k(const float* __restrict__ x,
                           const int* __restrict__ rowptr, const int* __restrict__ adj,
                           float* __restrict__ out, int n) {
    int gt = blockIdx.x * blockDim.x + threadIdx.x;
    int i = gt >> 5;
    int lane = gt & 31;
    if (i >= n) return;
    int b = rowptr[i], e = rowptr[i + 1];
    float acc = 0.f;
    for (int j = b; j < e; j++) {
        int s = adj[j];
        acc += __ldg(x + (size_t)s * EIN + lane);
    }
    float inv = 1.0f / (float)max(e - b, 1);
    out[(size_t)i * EIN + lane] = acc * inv;
}

// ---------------- mean gather: 128-dim, warp per node -----------------------
__global__ void gather128_k(const float* __restrict__ h,
                            const int* __restrict__ rowptr, const int* __restrict__ adj,
                            float* __restrict__ out, int n) {
    int gt = blockIdx.x * blockDim.x + threadIdx.x;
    int i = gt >> 5;
    int lane = gt & 31;
    if (i >= n) return;
    int b = rowptr[i], e = rowptr[i + 1];
    float4 acc = make_float4(0.f, 0.f, 0.f, 0.f);
    int j = b;
    for (; j + 1 < e; j += 2) {          // 2-way to raise MLP
        int s0 = adj[j], s1 = adj[j + 1];
        float4 v0 = ((const float4*)(h + (size_t)s0 * HH))[lane];
        float4 v1 = ((const float4*)(h + (size_t)s1 * HH))[lane];
        acc.x += v0.x + v1.x; acc.y += v0.y + v1.y;
        acc.z += v0.z + v1.z; acc.w += v0.w + v1.w;
    }
    if (j < e) {
        int s = adj[j];
        float4 v = ((const float4*)(h + (size_t)s * HH))[lane];
        acc.x += v.x; acc.y += v.y; acc.z += v.z; acc.w += v.w;
    }
    float inv = 1.0f / (float)max(e - b, 1);
    acc.x *= inv; acc.y *= inv; acc.z *= inv; acc.w *= inv;
    ((float4*)(out + (size_t)i * HH))[lane] = acc;
}

// ---------------- fused SAGE GEMM: out = relu([mean | x] @ [Wl;Wr] + b) -----
template <int KA, int KB>
__global__ void __launch_bounds__(256)
sage_gemm(const float* __restrict__ Aagg, const float* __restrict__ Ax,
          const float* __restrict__ Wl, const float* __restrict__ Wr,
          const float* __restrict__ bias, float* __restrict__ out, int n) {
    constexpr int K = KA + KB;
    constexpr int BM = 128, BN = 128, BK = 8;
    __shared__ float As[BK][BM + 4];
    __shared__ float Ws[BK][BN];
    int tid = threadIdx.x;
    int row0 = blockIdx.x * BM;

    int arow = tid >> 1;
    int acol = (tid & 1) * 4;
    int grow = row0 + arow;
    bool rvalid = grow < n;

    int wk = tid >> 5;
    int wcol = (tid & 31) * 4;

    int tx = tid & 15, ty = tid >> 4;
    float acc[8][8];
#pragma unroll
    for (int m = 0; m < 8; m++)
#pragma unroll
        for (int q = 0; q < 8; q++) acc[m][q] = 0.f;

    for (int k0 = 0; k0 < K; k0 += BK) {
        float4 av = make_float4(0.f, 0.f, 0.f, 0.f);
        int kg = k0 + acol;
        if (rvalid) {
            if (KB == 0 || kg < KA)
                av = *(const float4*)(Aagg + (size_t)grow * KA + kg);
            else
                av = *(const float4*)(Ax + (size_t)grow * KB + (kg - KA));
        }
        As[acol + 0][arow] = av.x;
        As[acol + 1][arow] = av.y;
        As[acol + 2][arow] = av.z;
        As[acol + 3][arow] = av.w;

        int kw = k0 + wk;
        float4 wv;
        if (KB == 0 || kw < KA) wv = *(const float4*)(Wl + (size_t)kw * BN + wcol);
        else                    wv = *(const float4*)(Wr + (size_t)(kw - KA) * BN + wcol);
        *(float4*)&Ws[wk][wcol] = wv;

        __syncthreads();
#pragma unroll
        for (int kk = 0; kk < BK; kk++) {
            float a[8], b[8];
#pragma unroll
            for (int m = 0; m < 8; m++) a[m] = As[kk][ty * 8 + m];
#pragma unroll
            for (int q = 0; q < 8; q++) b[q] = Ws[kk][tx * 8 + q];
#pragma unroll
            for (int m = 0; m < 8; m++)
#pragma unroll
                for (int q = 0; q < 8; q++) acc[m][q] += a[m] * b[q];
        }
        __syncthreads();
    }

    float bv[8];
#pragma unroll
    for (int q = 0; q < 8; q++) bv[q] = bias[tx * 8 + q];
#pragma unroll
    for (int m = 0; m < 8; m++) {
        int r = row0 + ty * 8 + m;
        if (r < n) {
#pragma unroll
            for (int q = 0; q < 8; q += 4) {
                float4 v;
                v.x = fmaxf(acc[m][q + 0] + bv[q + 0], 0.f);
                v.y = fmaxf(acc[m][q + 1] + bv[q + 1], 0.f);
                v.z = fmaxf(acc[m][q + 2] + bv[q + 2], 0.f);
                v.w = fmaxf(acc[m][q + 3] + bv[q + 3], 0.f);
                *(float4*)(out + (size_t)r * BN + tx * 8 + q) = v;
            }
        }
    }
}

// ---------------- fc head + aux layer1: warp per node -----------------------
__global__ void fc_a1_k(const float* __restrict__ h2,
                        const float* __restrict__ Wfc, const float* __restrict__ bfc,
                        const float* __restrict__ Wa1, const float* __restrict__ ba1,
                        float* __restrict__ d13, float* __restrict__ a1out, int n) {
    int gt = blockIdx.x * blockDim.x + threadIdx.x;
    int i = gt >> 5;
    int lane = gt & 31;
    if (i >= n) return;
    float4 h = ((const float4*)(h2 + (size_t)i * HH))[lane];
    int k = lane * 4;
    float s1 = h.x * Wfc[(k + 0) * 3 + 0] + h.y * Wfc[(k + 1) * 3 + 0]
             + h.z * Wfc[(k + 2) * 3 + 0] + h.w * Wfc[(k + 3) * 3 + 0];
    float s3 = h.x * Wfc[(k + 0) * 3 + 2] + h.y * Wfc[(k + 1) * 3 + 2]
             + h.z * Wfc[(k + 2) * 3 + 2] + h.w * Wfc[(k + 3) * 3 + 2];
#pragma unroll
    for (int off = 16; off > 0; off >>= 1) {
        s1 += __shfl_down_sync(0xffffffffu, s1, off);
        s3 += __shfl_down_sync(0xffffffffu, s3, off);
    }
    float d1 = __shfl_sync(0xffffffffu, s1, 0) + bfc[0];
    float d3 = __shfl_sync(0xffffffffu, s3, 0) + bfc[2];
    if (lane == 0) {
        d13[(size_t)i * 2 + 0] = d1;
        d13[(size_t)i * 2 + 1] = d3;
    }
    float4 w0 = *(const float4*)(Wa1 + k);
    float4 w1 = *(const float4*)(Wa1 + HH + k);
    float4 b  = *(const float4*)(ba1 + k);
    float4 o;
    o.x = fmaxf(d1 * w0.x + d3 * w1.x + b.x, 0.f);
    o.y = fmaxf(d1 * w0.y + d3 * w1.y + b.y, 0.f);
    o.z = fmaxf(d1 * w0.z + d3 * w1.z + b.z, 0.f);
    o.w = fmaxf(d1 * w0.w + d3 * w1.w + b.w, 0.f);
    *(float4*)(a1out + (size_t)i * HH + k) = o;
}

// ---------------- aux output + group accumulation: warp per node ------------
__global__ void final_k(const float* __restrict__ a2,
                        const float* __restrict__ Wao, const float* __restrict__ bao,
                        const float* __restrict__ d13,
                        const int* __restrict__ batch,
                        float* __restrict__ g, int n) {
    __shared__ float sg[GG * 4];
    int tid = threadIdx.x;
    for (int j = tid; j < GG * 4; j += blockDim.x) sg[j] = 0.f;
    __syncthreads();

    int gt = blockIdx.x * blockDim.x + tid;
    int i = gt >> 5;
    int lane = gt & 31;
    if (i < n) {
        float4 v = ((const float4*)(a2 + (size_t)i * HH))[lane];
        float4 w = ((const float4*)Wao)[lane];
        float s = v.x * w.x + v.y * w.y + v.z * w.z + v.w * w.w;
#pragma unroll
        for (int off = 16; off > 0; off >>= 1)
            s += __shfl_down_sync(0xffffffffu, s, off);
        if (lane == 0) {
            float aux = s + bao[0];
            int b = batch[i];
            atomicAdd(&sg[b * 4 + 0], d13[(size_t)i * 2 + 0]);
            atomicAdd(&sg[b * 4 + 1], aux);
            atomicAdd(&sg[b * 4 + 2], d13[(size_t)i * 2 + 1]);
            atomicAdd(&sg[b * 4 + 3], 1.0f);
        }
    }
    __syncthreads();
    for (int j = tid; j < GG * 4; j += blockDim.x)
        if (sg[j] != 0.f) atomicAdd(&g[j], sg[j]);
}

// ---------------- finalize: group mean --------------------------------------
__global__ void finalize_k(const float* __restrict__ g, float* __restrict__ out) {
    int t = blockIdx.x * blockDim.x + threadIdx.x;
    if (t < GG * 3) {
        int grp = t / 3, c = t % 3;
        out[t] = g[grp * 4 + c] / fmaxf(g[grp * 4 + 3], 1.0f);
    }
}

// ---------------- launch -----------------------------------------------------
extern "C" void kernel_launch(void* const* d_in, const int* in_sizes, int n_in,
                              void* d_out, int out_size) {
    const float* x   = (const float*)d_in[0];
    const int*   ei  = (const int*)d_in[1];   // int32 (JAX x64 disabled)
    const int*   bat = (const int*)d_in[2];
    const float* Wl0 = (const float*)d_in[3];
    const float* bl0 = (const float*)d_in[4];
    const float* Wr0 = (const float*)d_in[5];
    const float* Wl1 = (const float*)d_in[6];
    const float* bl1 = (const float*)d_in[7];
    const float* Wr1 = (const float*)d_in[8];
    const float* Wl2 = (const float*)d_in[9];
    const float* bl2 = (const float*)d_in[10];
    const float* Wr2 = (const float*)d_in[11];
    const float* Wfc = (const float*)d_in[12];
    const float* bfc = (const float*)d_in[13];
    const float* Wa1 = (const float*)d_in[14];
    const float* ba1 = (const float*)d_in[15];
    const float* Wa2 = (const float*)d_in[16];
    const float* ba2 = (const float*)d_in[17];
    const float* Wao = (const float*)d_in[18];
    const float* bao = (const float*)d_in[19];
    float* out = (float*)d_out;

    int N = in_sizes[0] / EIN;
    int E = in_sizes[1] / 2;
    const int* src = ei;
    const int* dst = ei + E;

    void* p;
    cudaGetSymbolAddress(&p, d_S1);     float* S1  = (float*)p;
    cudaGetSymbolAddress(&p, d_S2);     float* S2  = (float*)p;
    cudaGetSymbolAddress(&p, d_S3);     float* S3  = (float*)p;
    cudaGetSymbolAddress(&p, d_d13);    float* d13 = (float*)p;
    cudaGetSymbolAddress(&p, d_g);      float* g   = (float*)p;
    cudaGetSymbolAddress(&p, d_deg);    int* deg    = (int*)p;
    cudaGetSymbolAddress(&p, d_rowptr); int* rowptr = (int*)p;
    cudaGetSymbolAddress(&p, d_cursor); int* cursor = (int*)p;
    cudaGetSymbolAddress(&p, d_adj);    int* adj    = (int*)p;
    cudaGetSymbolAddress(&p, d_blksum); int* blksum = (int*)p;

    int nb = (N + 1023) / 1024;

    // --- CSR build ---
    zero_deg_g<<<(N + 255) / 256, 256>>>(deg, g, N);
    hist_k<<<(E + 255) / 256, 256>>>(dst, deg, E);
    scan1_k<<<nb, 1024>>>(deg, rowptr, blksum, N);
    scan2_k<<<1, 32>>>(blksum, nb);
    scan3_k<<<(N + 1023) / 1024, 1024>>>(rowptr, blksum, cursor, N, E);
    fill_k<<<(E + 255) / 256, 256>>>(src, dst, cursor, adj, E);

    int wgrid = ((size_t)N * 32 + 255) / 256;
    int gblk = (N + 127) / 128;

    // --- layer 0 ---
    gather32_k<<<wgrid, 256>>>(x, rowptr, adj, S1, N);
    sage_gemm<EIN, EIN><<<gblk, 256>>>(S1, x, Wl0, Wr0, bl0, S2, N);

    // --- layer 1 ---
    gather128_k<<<wgrid, 256>>>(S2, rowptr, adj, S1, N);
    sage_gemm<HH, HH><<<gblk, 256>>>(S1, S2, Wl1, Wr1, bl1, S3, N);

    // --- layer 2 ---
    gather128_k<<<wgrid, 256>>>(S3, rowptr, adj, S1, N);
    sage_gemm<HH, HH><<<gblk, 256>>>(S1, S3, Wl2, Wr2, bl2, S2, N);

    // --- heads ---
    fc_a1_k<<<wgrid, 256>>>(S2, Wfc, bfc, Wa1, ba1, d13, S1, N);
    sage_gemm<HH, 0><<<gblk, 256>>>(S1, nullptr, Wa2, nullptr, ba2, S3, N);
    final_k<<<wgrid, 256>>>(S3, Wao, bao, d13, bat, g, N);
    finalize_k<<<1, 256>>>(g, out);
}

// round 5
// speedup vs baseline: 2.3436x; 1.6316x over previous
#include <cuda_runtime.h>
#include <cstdint>

#define NN 100000
#define EE 1600000
#define HH 128
#define GG 64
#define EIN 32

// ---------------- static device scratch -------------------------------------
__device__ __align__(16) float d_S1[(size_t)NN * HH];   // mean / a1 scratch
__device__ __align__(16) float d_S2[(size_t)NN * HH];   // h0 / h2
__device__ __align__(16) float d_S3[(size_t)NN * HH];   // h1 / a2
__device__ __align__(16) float d_d13[(size_t)NN * 2];
__device__ __align__(16) float d_g[GG * 4];
__device__ int d_deg[NN];
__device__ int d_rowptr[NN + 1];
__device__ int d_cursor[NN];
__device__ int d_adj[EE];
__device__ int d_blksum[256];

// ---------------- CSR build --------------------------------------------------
__global__ void zero_deg_g(int* __restrict__ deg, float* __restrict__ g, int n) {
    int i = blockIdx.x * blockDim.x + threadIdx.x;
    if (i < n) deg[i] = 0;
    if (i < GG * 4) g[i] = 0.f;
}

__global__ void hist_k(const int* __restrict__ dst, int* __restrict__ deg, int E) {
    int e = blockIdx.x * blockDim.x + threadIdx.x;
    if (e < E) atomicAdd(&deg[dst[e]], 1);
}

__global__ void scan1_k(const int* __restrict__ deg, int* __restrict__ excl,
                        int* __restrict__ blksum, int n) {
    __shared__ int sh[1024];
    int tid = threadIdx.x;
    int i = blockIdx.x * 1024 + tid;
    int v = (i < n) ? deg[i] : 0;
    sh[tid] = v;
    __syncthreads();
#pragma unroll
    for (int off = 1; off < 1024; off <<= 1) {
        int t = (tid >= off) ? sh[tid - off] : 0;
        __syncthreads();
        sh[tid] += t;
        __syncthreads();
    }
    if (i < n) excl[i] = sh[tid] - v;
    if (tid == 1023) blksum[blockIdx.x] = sh[1023];
}

__global__ void scan2_k(int* __restrict__ blksum, int nb) {
    if (threadIdx.x == 0) {
        int run = 0;
        for (int b = 0; b < nb; b++) { int t = blksum[b]; blksum[b] = run; run += t; }
    }
}

__global__ void scan3_k(int* __restrict__ rowptr, const int* __restrict__ blksum,
                        int* __restrict__ cursor, int n, int E) {
    int i = blockIdx.x * blockDim.x + threadIdx.x;
    if (i < n) {
        int r = rowptr[i] + blksum[i >> 10];
        rowptr[i] = r;
        cursor[i] = r;
    }
    if (i == 0) rowptr[n] = E;
}

__global__ void fill_k(const int* __restrict__ src, const int* __restrict__ dst,
                       int* __restrict__ cursor, int* __restrict__ adj, int E) {
    int e = blockIdx.x * blockDim.x + threadIdx.x;
    if (e < E) {
        int slot = atomicAdd(&cursor[dst[e]], 1);
        adj[slot] = src[e];
    }
}

// ---------------- mean gather: 32-dim (layer 0), warp per node --------------
__global__ void gather32_k(const float* __restrict__ x,
                           const int* __restrict__ rowptr, const int* __restrict__ adj,
                           float* __restrict__ out, int n) {
    int gt = blockIdx.x * blockDim.x + threadIdx.x;
    int i = gt >> 5;
    int lane = gt & 31;
    if (i >= n) return;
    int b = rowptr[i], e = rowptr[i + 1];
    float acc = 0.f;
    for (int j = b; j < e; j++) {
        int s = adj[j];
        acc += __ldg(x + (size_t)s * EIN + lane);
    }
    float inv = 1.0f / (float)max(e - b, 1);
    out[(size_t)i * EIN + lane] = acc * inv;
}

// ---------------- mean gather: 128-dim, warp per node -----------------------
__global__ void gather128_k(const float* __restrict__ h,
                            const int* __restrict__ rowptr, const int* __restrict__ adj,
                            float* __restrict__ out, int n) {
    int gt = blockIdx.x * blockDim.x + threadIdx.x;
    int i = gt >> 5;
    int lane = gt & 31;
    if (i >= n) return;
    int b = rowptr[i], e = rowptr[i + 1];
    float4 acc = make_float4(0.f, 0.f, 0.f, 0.f);
    int j = b;
    for (; j + 1 < e; j += 2) {
        int s0 = adj[j], s1 = adj[j + 1];
        float4 v0 = ((const float4*)(h + (size_t)s0 * HH))[lane];
        float4 v1 = ((const float4*)(h + (size_t)s1 * HH))[lane];
        acc.x += v0.x + v1.x; acc.y += v0.y + v1.y;
        acc.z += v0.z + v1.z; acc.w += v0.w + v1.w;
    }
    if (j < e) {
        int s = adj[j];
        float4 v = ((const float4*)(h + (size_t)s * HH))[lane];
        acc.x += v.x; acc.y += v.y; acc.z += v.z; acc.w += v.w;
    }
    float inv = 1.0f / (float)max(e - b, 1);
    acc.x *= inv; acc.y *= inv; acc.z *= inv; acc.w *= inv;
    ((float4*)(out + (size_t)i * HH))[lane] = acc;
}

// ---------------- tf32 helpers ----------------------------------------------
__device__ __forceinline__ uint32_t f2tf32(float x) {
    uint32_t r;
    asm("cvt.rna.tf32.f32 %0, %1;" : "=r"(r) : "f"(x));
    return r;
}

__device__ __forceinline__ void mma_tf32(float* d, const uint32_t* a, const uint32_t* b) {
    asm volatile(
        "mma.sync.aligned.m16n8k8.row.col.f32.tf32.tf32.f32 "
        "{%0,%1,%2,%3}, {%4,%5,%6,%7}, {%8,%9}, {%0,%1,%2,%3};"
        : "+f"(d[0]), "+f"(d[1]), "+f"(d[2]), "+f"(d[3])
        : "r"(a[0]), "r"(a[1]), "r"(a[2]), "r"(a[3]), "r"(b[0]), "r"(b[1]));
}

// ---------------- tensor-core SAGE GEMM (tf32) ------------------------------
// out[M,128] = relu([Aagg | Ax] @ [Wl; Wr] + bias)   K = KA + KB
// BM=128 BN=128 BK=32, 8 warps, warp tile 64x32, m16n8k8 tf32 MMA.
#define APAD 36   // As row stride (words): conflict-free frag reads (4g+t banks)
#define WPAD 136  // Ws row stride (words): conflict-free frag reads (8t+g banks)

template <int KA, int KB>
__global__ void __launch_bounds__(256, 2)
sage_gemm_tc(const float* __restrict__ Aagg, const float* __restrict__ Ax,
             const float* __restrict__ Wl, const float* __restrict__ Wr,
             const float* __restrict__ bias, float* __restrict__ out, int n) {
    constexpr int K = KA + KB;
    constexpr int BK = 32;
    __shared__ uint32_t As[128 * APAD];
    __shared__ uint32_t Ws[BK * WPAD];

    int tid = threadIdx.x;
    int lane = tid & 31;
    int wid = tid >> 5;
    int warpM = wid >> 2;       // 0..1 -> m offset *64
    int warpN = wid & 3;        // 0..3 -> n offset *32
    int row0 = blockIdx.x * 128;

    // A-load mapping: row = tid>>1 (0..127), half = tid&1 -> k offsets half*16 + j*4
    int arow = tid >> 1;
    int ahalf = tid & 1;
    int grow = row0 + arow;
    bool rvalid = grow < n;

    // W-load mapping: k = tid>>3 (0..31), 4 float4 at n = (tid&7)*16 + j*4
    int wk = tid >> 3;
    int wn0 = (tid & 7) * 16;

    float acc[4][4][4];
#pragma unroll
    for (int mt = 0; mt < 4; mt++)
#pragma unroll
        for (int nt = 0; nt < 4; nt++)
#pragma unroll
            for (int q = 0; q < 4; q++) acc[mt][nt][q] = 0.f;

    for (int k0 = 0; k0 < K; k0 += BK) {
        // ---- load A tile (128 x 32) ----
#pragma unroll
        for (int j = 0; j < 4; j++) {
            int kg = k0 + ahalf * 16 + j * 4;
            float4 av = make_float4(0.f, 0.f, 0.f, 0.f);
            if (rvalid) {
                if (KB == 0 || kg < KA)
                    av = *(const float4*)(Aagg + (size_t)grow * KA + kg);
                else
                    av = *(const float4*)(Ax + (size_t)grow * KB + (kg - KA));
            }
            uint32_t* dstp = &As[arow * APAD + ahalf * 16 + j * 4];
            dstp[0] = f2tf32(av.x); dstp[1] = f2tf32(av.y);
            dstp[2] = f2tf32(av.z); dstp[3] = f2tf32(av.w);
        }
        // ---- load W tile (32 x 128) ----
#pragma unroll
        for (int j = 0; j < 4; j++) {
            int kw = k0 + wk;
            int nn = wn0 + j * 4;
            float4 wv;
            if (KB == 0 || kw < KA) wv = *(const float4*)(Wl + (size_t)kw * 128 + nn);
            else                    wv = *(const float4*)(Wr + (size_t)(kw - KA) * 128 + nn);
            uint32_t* dstp = &Ws[wk * WPAD + nn];
            dstp[0] = f2tf32(wv.x); dstp[1] = f2tf32(wv.y);
            dstp[2] = f2tf32(wv.z); dstp[3] = f2tf32(wv.w);
        }
        __syncthreads();

        // ---- MMA: 4 k-chunks of 8 ----
#pragma unroll
        for (int kk = 0; kk < 4; kk++) {
            uint32_t af[4][4];
            int kcol = kk * 8 + (lane & 3);
            int r = warpM * 64 + (lane >> 2);
#pragma unroll
            for (int mt = 0; mt < 4; mt++) {
                int rb = r + mt * 16;
                af[mt][0] = As[rb * APAD + kcol];
                af[mt][1] = As[(rb + 8) * APAD + kcol];
                af[mt][2] = As[rb * APAD + kcol + 4];
                af[mt][3] = As[(rb + 8) * APAD + kcol + 4];
            }
            uint32_t bf[4][2];
            int krow = kk * 8 + (lane & 3);
            int nb = warpN * 32 + (lane >> 2);
#pragma unroll
            for (int nt = 0; nt < 4; nt++) {
                bf[nt][0] = Ws[krow * WPAD + nb + nt * 8];
                bf[nt][1] = Ws[(krow + 4) * WPAD + nb + nt * 8];
            }
#pragma unroll
            for (int mt = 0; mt < 4; mt++)
#pragma unroll
                for (int nt = 0; nt < 4; nt++)
                    mma_tf32(acc[mt][nt], af[mt], bf[nt]);
        }
        __syncthreads();
    }

    // ---- epilogue: bias + relu, float2 stores ----
#pragma unroll
    for (int nt = 0; nt < 4; nt++) {
        int c = warpN * 32 + nt * 8 + (lane & 3) * 2;
        float b0 = bias[c], b1 = bias[c + 1];
#pragma unroll
        for (int mt = 0; mt < 4; mt++) {
            int r0 = row0 + warpM * 64 + mt * 16 + (lane >> 2);
            if (r0 < n) {
                float2 v;
                v.x = fmaxf(acc[mt][nt][0] + b0, 0.f);
                v.y = fmaxf(acc[mt][nt][1] + b1, 0.f);
                *(float2*)(out + (size_t)r0 * 128 + c) = v;
            }
            int r1 = r0 + 8;
            if (r1 < n) {
                float2 v;
                v.x = fmaxf(acc[mt][nt][2] + b0, 0.f);
                v.y = fmaxf(acc[mt][nt][3] + b1, 0.f);
                *(float2*)(out + (size_t)r1 * 128 + c) = v;
            }
        }
    }
}

// ---------------- fc head + aux layer1: warp per node -----------------------
__global__ void fc_a1_k(const float* __restrict__ h2,
                        const float* __restrict__ Wfc, const float* __restrict__ bfc,
                        const float* __restrict__ Wa1, const float* __restrict__ ba1,
                        float* __restrict__ d13, float* __restrict__ a1out, int n) {
    int gt = blockIdx.x * blockDim.x + threadIdx.x;
    int i = gt >> 5;
    int lane = gt & 31;
    if (i >= n) return;
    float4 h = ((const float4*)(h2 + (size_t)i * HH))[lane];
    int k = lane * 4;
    float s1 = h.x * Wfc[(k + 0) * 3 + 0] + h.y * Wfc[(k + 1) * 3 + 0]
             + h.z * Wfc[(k + 2) * 3 + 0] + h.w * Wfc[(k + 3) * 3 + 0];
    float s3 = h.x * Wfc[(k + 0) * 3 + 2] + h.y * Wfc[(k + 1) * 3 + 2]
             + h.z * Wfc[(k + 2) * 3 + 2] + h.w * Wfc[(k + 3) * 3 + 2];
#pragma unroll
    for (int off = 16; off > 0; off >>= 1) {
        s1 += __shfl_down_sync(0xffffffffu, s1, off);
        s3 += __shfl_down_sync(0xffffffffu, s3, off);
    }
    float d1 = __shfl_sync(0xffffffffu, s1, 0) + bfc[0];
    float d3 = __shfl_sync(0xffffffffu, s3, 0) + bfc[2];
    if (lane == 0) {
        d13[(size_t)i * 2 + 0] = d1;
        d13[(size_t)i * 2 + 1] = d3;
    }
    float4 w0 = *(const float4*)(Wa1 + k);
    float4 w1 = *(const float4*)(Wa1 + HH + k);
    float4 b  = *(const float4*)(ba1 + k);
    float4 o;
    o.x = fmaxf(d1 * w0.x + d3 * w1.x + b.x, 0.f);
    o.y = fmaxf(d1 * w0.y + d3 * w1.y + b.y, 0.f);
    o.z = fmaxf(d1 * w0.z + d3 * w1.z + b.z, 0.f);
    o.w = fmaxf(d1 * w0.w + d3 * w1.w + b.w, 0.f);
    *(float4*)(a1out + (size_t)i * HH + k) = o;
}

// ---------------- aux output + group accumulation: warp per node ------------
__global__ void final_k(const float* __restrict__ a2,
                        const float* __restrict__ Wao, const float* __restrict__ bao,
                        const float* __restrict__ d13,
                        const int* __restrict__ batch,
                        float* __restrict__ g, int n) {
    __shared__ float sg[GG * 4];
    int tid = threadIdx.x;
    for (int j = tid; j < GG * 4; j += blockDim.x) sg[j] = 0.f;
    __syncthreads();

    int gt = blockIdx.x * blockDim.x + tid;
    int i = gt >> 5;
    int lane = gt & 31;
    if (i < n) {
        float4 v = ((const float4*)(a2 + (size_t)i * HH))[lane];
        float4 w = ((const float4*)Wao)[lane];
        float s = v.x * w.x + v.y * w.y + v.z * w.z + v.w * w.w;
#pragma unroll
        for (int off = 16; off > 0; off >>= 1)
            s += __shfl_down_sync(0xffffffffu, s, off);
        if (lane == 0) {
            float aux = s + bao[0];
            int b = batch[i];
            atomicAdd(&sg[b * 4 + 0], d13[(size_t)i * 2 + 0]);
            atomicAdd(&sg[b * 4 + 1], aux);
            atomicAdd(&sg[b * 4 + 2], d13[(size_t)i * 2 + 1]);
            atomicAdd(&sg[b * 4 + 3], 1.0f);
        }
    }
    __syncthreads();
    for (int j = tid; j < GG * 4; j += blockDim.x)
        if (sg[j] != 0.f) atomicAdd(&g[j], sg[j]);
}

// ---------------- finalize: group mean --------------------------------------
__global__ void finalize_k(const float* __restrict__ g, float* __restrict__ out) {
    int t = blockIdx.x * blockDim.x + threadIdx.x;
    if (t < GG * 3) {
        int grp = t / 3, c = t % 3;
        out[t] = g[grp * 4 + c] / fmaxf(g[grp * 4 + 3], 1.0f);
    }
}

// ---------------- launch -----------------------------------------------------
extern "C" void kernel_launch(void* const* d_in, const int* in_sizes, int n_in,
                              void* d_out, int out_size) {
    const float* x   = (const float*)d_in[0];
    const int*   ei  = (const int*)d_in[1];
    const int*   bat = (const int*)d_in[2];
    const float* Wl0 = (const float*)d_in[3];
    const float* bl0 = (const float*)d_in[4];
    const float* Wr0 = (const float*)d_in[5];
    const float* Wl1 = (const float*)d_in[6];
    const float* bl1 = (const float*)d_in[7];
    const float* Wr1 = (const float*)d_in[8];
    const float* Wl2 = (const float*)d_in[9];
    const float* bl2 = (const float*)d_in[10];
    const float* Wr2 = (const float*)d_in[11];
    const float* Wfc = (const float*)d_in[12];
    const float* bfc = (const float*)d_in[13];
    const float* Wa1 = (const float*)d_in[14];
    const float* ba1 = (const float*)d_in[15];
    const float* Wa2 = (const float*)d_in[16];
    const float* ba2 = (const float*)d_in[17];
    const float* Wao = (const float*)d_in[18];
    const float* bao = (const float*)d_in[19];
    float* out = (float*)d_out;

    int N = in_sizes[0] / EIN;
    int E = in_sizes[1] / 2;
    const int* src = ei;
    const int* dst = ei + E;

    void* p;
    cudaGetSymbolAddress(&p, d_S1);     float* S1  = (float*)p;
    cudaGetSymbolAddress(&p, d_S2);     float* S2  = (float*)p;
    cudaGetSymbolAddress(&p, d_S3);     float* S3  = (float*)p;
    cudaGetSymbolAddress(&p, d_d13);    float* d13 = (float*)p;
    cudaGetSymbolAddress(&p, d_g);      float* g   = (float*)p;
    cudaGetSymbolAddress(&p, d_deg);    int* deg    = (int*)p;
    cudaGetSymbolAddress(&p, d_rowptr); int* rowptr = (int*)p;
    cudaGetSymbolAddress(&p, d_cursor); int* cursor = (int*)p;
    cudaGetSymbolAddress(&p, d_adj);    int* adj    = (int*)p;
    cudaGetSymbolAddress(&p, d_blksum); int* blksum = (int*)p;

    int nb = (N + 1023) / 1024;

    // --- CSR build ---
    zero_deg_g<<<(N + 255) / 256, 256>>>(deg, g, N);
    hist_k<<<(E + 255) / 256, 256>>>(dst, deg, E);
    scan1_k<<<nb, 1024>>>(deg, rowptr, blksum, N);
    scan2_k<<<1, 32>>>(blksum, nb);
    scan3_k<<<(N + 1023) / 1024, 1024>>>(rowptr, blksum, cursor, N, E);
    fill_k<<<(E + 255) / 256, 256>>>(src, dst, cursor, adj, E);

    int wgrid = ((size_t)N * 32 + 255) / 256;
    int gblk = (N + 127) / 128;

    // --- layer 0 ---
    gather32_k<<<wgrid, 256>>>(x, rowptr, adj, S1, N);
    sage_gemm_tc<EIN, EIN><<<gblk, 256>>>(S1, x, Wl0, Wr0, bl0, S2, N);

    // --- layer 1 ---
    gather128_k<<<wgrid, 256>>>(S2, rowptr, adj, S1, N);
    sage_gemm_tc<HH, HH><<<gblk, 256>>>(S1, S2, Wl1, Wr1, bl1, S3, N);

    // --- layer 2 ---
    gather128_k<<<wgrid, 256>>>(S3, rowptr, adj, S1, N);
    sage_gemm_tc<HH, HH><<<gblk, 256>>>(S1, S3, Wl2, Wr2, bl2, S2, N);

    // --- heads ---
    fc_a1_k<<<wgrid, 256>>>(S2, Wfc, bfc, Wa1, ba1, d13, S1, N);
    sage_gemm_tc<HH, 0><<<gblk, 256>>>(S1, nullptr, Wa2, nullptr, ba2, S3, N);
    final_k<<<wgrid, 256>>>(S3, Wao, bao, d13, bat, g, N);
    finalize_k<<<1, 256>>>(g, out);
}

// round 10
// speedup vs baseline: 3.0423x; 1.2981x over previous
#include <cuda_runtime.h>
#include <cuda_fp16.h>
#include <cstdint>

#define NN 100000
#define EE 1600000
#define HH 128
#define GG 64
#define EIN 32

// ---------------- static device scratch -------------------------------------
__device__ __align__(16) __half d_M[(size_t)NN * HH];    // mean scratch / a1
__device__ __align__(16) __half d_HA[(size_t)NN * HH];   // h0 / h2
__device__ __align__(16) __half d_HB[(size_t)NN * HH];   // h1 / a2
__device__ __align__(16) __half d_xh[(size_t)NN * EIN];  // x in fp16
__device__ __align__(16) float d_d13[(size_t)NN * 2];
__device__ __align__(16) float d_g[GG * 4];
__device__ int d_deg[NN];
__device__ int d_rowptr[NN + 1];
__device__ int d_cursor[NN];
__device__ int d_adj[EE];
__device__ int d_blksum[256];

// ---------------- CSR build --------------------------------------------------
__global__ void zero_deg_g(int* __restrict__ deg, float* __restrict__ g, int n) {
    int i = blockIdx.x * blockDim.x + threadIdx.x;
    if (i < n) deg[i] = 0;
    if (i < GG * 4) g[i] = 0.f;
}

__global__ void cvt_x_k(const float4* __restrict__ x4, __half2* __restrict__ xh2, int n4) {
    int stride = gridDim.x * blockDim.x;
    for (int i = blockIdx.x * blockDim.x + threadIdx.x; i < n4; i += stride) {
        float4 v = x4[i];
        xh2[i * 2 + 0] = __floats2half2_rn(v.x, v.y);
        xh2[i * 2 + 1] = __floats2half2_rn(v.z, v.w);
    }
}

__global__ void hist_k(const int* __restrict__ dst, int* __restrict__ deg, int E) {
    int e = blockIdx.x * blockDim.x + threadIdx.x;
    if (e < E) atomicAdd(&deg[dst[e]], 1);
}

__global__ void scan1_k(const int* __restrict__ deg, int* __restrict__ excl,
                        int* __restrict__ blksum, int n) {
    __shared__ int sh[1024];
    int tid = threadIdx.x;
    int i = blockIdx.x * 1024 + tid;
    int v = (i < n) ? deg[i] : 0;
    sh[tid] = v;
    __syncthreads();
#pragma unroll
    for (int off = 1; off < 1024; off <<= 1) {
        int t = (tid >= off) ? sh[tid - off] : 0;
        __syncthreads();
        sh[tid] += t;
        __syncthreads();
    }
    if (i < n) excl[i] = sh[tid] - v;
    if (tid == 1023) blksum[blockIdx.x] = sh[1023];
}

__global__ void scan2_k(int* __restrict__ blksum, int nb) {
    __shared__ int sh[128];
    int tid = threadIdx.x;
    int v = (tid < nb) ? blksum[tid] : 0;
    sh[tid] = v;
    __syncthreads();
#pragma unroll
    for (int off = 1; off < 128; off <<= 1) {
        int t = (tid >= off) ? sh[tid - off] : 0;
        __syncthreads();
        sh[tid] += t;
        __syncthreads();
    }
    if (tid < nb) blksum[tid] = sh[tid] - v;
}

__global__ void scan3_k(int* __restrict__ rowptr, const int* __restrict__ blksum,
                        int* __restrict__ cursor, int n, int E) {
    int i = blockIdx.x * blockDim.x + threadIdx.x;
    if (i < n) {
        int r = rowptr[i] + blksum[i >> 10];
        rowptr[i] = r;
        cursor[i] = r;
    }
    if (i == 0) rowptr[n] = E;
}

__global__ void fill_k(const int* __restrict__ src, const int* __restrict__ dst,
                       int* __restrict__ cursor, int* __restrict__ adj, int E) {
    int e = blockIdx.x * blockDim.x + threadIdx.x;
    if (e < E) {
        int slot = atomicAdd(&cursor[dst[e]], 1);
        adj[slot] = src[e];
    }
}

// ---------------- mean gather: 32-dim fp16, warp per node -------------------
__global__ void gather32h_k(const __half* __restrict__ xh,
                            const int* __restrict__ rowptr, const int* __restrict__ adj,
                            __half* __restrict__ out, int n) {
    int gt = blockIdx.x * blockDim.x + threadIdx.x;
    int i = gt >> 5;
    int lane = gt & 31;
    if (i >= n) return;
    int b = rowptr[i], e = rowptr[i + 1];
    float acc = 0.f;
    int j = b;
    for (; j + 3 < e; j += 4) {
        int s0 = adj[j], s1 = adj[j + 1], s2 = adj[j + 2], s3 = adj[j + 3];
        acc += __half2float(xh[(size_t)s0 * EIN + lane])
             + __half2float(xh[(size_t)s1 * EIN + lane])
             + __half2float(xh[(size_t)s2 * EIN + lane])
             + __half2float(xh[(size_t)s3 * EIN + lane]);
    }
    for (; j < e; j++)
        acc += __half2float(xh[(size_t)adj[j] * EIN + lane]);
    float inv = 1.0f / (float)max(e - b, 1);
    out[(size_t)i * EIN + lane] = __float2half_rn(acc * inv);
}

// ---------------- mean gather: 128-dim fp16, warp per node ------------------
__global__ void gather128h_k(const __half* __restrict__ h,
                             const int* __restrict__ rowptr, const int* __restrict__ adj,
                             __half* __restrict__ out, int n) {
    int gt = blockIdx.x * blockDim.x + threadIdx.x;
    int i = gt >> 5;
    int lane = gt & 31;
    if (i >= n) return;
    int b = rowptr[i], e = rowptr[i + 1];
    float ax = 0.f, ay = 0.f, az = 0.f, aw = 0.f;
    int j = b;
    for (; j + 3 < e; j += 4) {
#pragma unroll
        for (int u = 0; u < 4; u++) {
            int s = adj[j + u];
            uint2 v = ((const uint2*)(h + (size_t)s * HH))[lane];
            float2 f0 = __half22float2(*(__half2*)&v.x);
            float2 f1 = __half22float2(*(__half2*)&v.y);
            ax += f0.x; ay += f0.y; az += f1.x; aw += f1.y;
        }
    }
    for (; j < e; j++) {
        int s = adj[j];
        uint2 v = ((const uint2*)(h + (size_t)s * HH))[lane];
        float2 f0 = __half22float2(*(__half2*)&v.x);
        float2 f1 = __half22float2(*(__half2*)&v.y);
        ax += f0.x; ay += f0.y; az += f1.x; aw += f1.y;
    }
    float inv = 1.0f / (float)max(e - b, 1);
    __half2 o0 = __floats2half2_rn(ax * inv, ay * inv);
    __half2 o1 = __floats2half2_rn(az * inv, aw * inv);
    uint2 st;
    st.x = *(uint32_t*)&o0; st.y = *(uint32_t*)&o1;
    ((uint2*)(out + (size_t)i * HH))[lane] = st;
}

// ---------------- fp16 MMA helpers ------------------------------------------
__device__ __forceinline__ uint32_t smem_u32(const void* p) {
    return (uint32_t)__cvta_generic_to_shared(p);
}
__device__ __forceinline__ void ldmatrix_x4(uint32_t& r0, uint32_t& r1,
                                            uint32_t& r2, uint32_t& r3, uint32_t addr) {
    asm volatile("ldmatrix.sync.aligned.m8n8.x4.shared.b16 {%0,%1,%2,%3}, [%4];"
                 : "=r"(r0), "=r"(r1), "=r"(r2), "=r"(r3) : "r"(addr));
}
__device__ __forceinline__ void ldmatrix_x2t(uint32_t& r0, uint32_t& r1, uint32_t addr) {
    asm volatile("ldmatrix.sync.aligned.m8n8.x2.trans.shared.b16 {%0,%1}, [%2];"
                 : "=r"(r0), "=r"(r1) : "r"(addr));
}
__device__ __forceinline__ void mma_f16(float* d, const uint32_t* a, const uint32_t* b) {
    asm volatile(
        "mma.sync.aligned.m16n8k16.row.col.f32.f16.f16.f32 "
        "{%0,%1,%2,%3}, {%4,%5,%6,%7}, {%8,%9}, {%0,%1,%2,%3};"
        : "+f"(d[0]), "+f"(d[1]), "+f"(d[2]), "+f"(d[3])
        : "r"(a[0]), "r"(a[1]), "r"(a[2]), "r"(a[3]), "r"(b[0]), "r"(b[1]));
}

// ---------------- fp16 tensor-core SAGE GEMM --------------------------------
// out[M,128](fp16) = relu([Aagg | Ax](fp16) @ [Wl;Wr](fp32->fp16) + bias)
// BM=128 BN=128 BK=32, 8 warps, warp tile 64x32, m16n8k16.
#define AS 40    // As row stride (halves): banks {20r%32} distinct
#define WS 136   // Ws row stride (halves): banks {4k%32} distinct

template <int KA, int KB>
__global__ void __launch_bounds__(256)
sage_gemm_h(const __half* __restrict__ Aagg, const __half* __restrict__ Ax,
            const float* __restrict__ Wl, const float* __restrict__ Wr,
            const float* __restrict__ bias, __half* __restrict__ out, int n) {
    constexpr int K = KA + KB;
    __shared__ __half As[128 * AS];
    __shared__ __half Ws[32 * WS];

    int tid = threadIdx.x;
    int lane = tid & 31;
    int wid = tid >> 5;
    int warpM = wid >> 2;     // 0..1 -> m*64
    int warpN = wid & 3;      // 0..3 -> n*32
    int row0 = blockIdx.x * 128;

    int arow = tid >> 1;
    int ahalf = tid & 1;      // 16-half chunk (32 bytes)
    int grow = row0 + arow;
    bool rvalid = grow < n;

    int wk = tid >> 3;        // 0..31
    int wn0 = (tid & 7) * 16;

    float acc[4][4][4];
#pragma unroll
    for (int mt = 0; mt < 4; mt++)
#pragma unroll
        for (int nt = 0; nt < 4; nt++)
#pragma unroll
            for (int q = 0; q < 4; q++) acc[mt][nt][q] = 0.f;

    for (int k0 = 0; k0 < K; k0 += 32) {
        // ---- A tile (128 x 32 fp16): each thread 16 halves = 2 x uint4 ----
        const __half* Asrc; int kloc, astr;
        if (KB == 0 || k0 < KA) { Asrc = Aagg; kloc = k0; astr = KA; }
        else                    { Asrc = Ax; kloc = k0 - KA; astr = KB; }
        uint4 u0 = make_uint4(0u, 0u, 0u, 0u);
        uint4 u1 = make_uint4(0u, 0u, 0u, 0u);
        if (rvalid) {
            const __half* base = Asrc + (size_t)grow * astr + kloc + ahalf * 16;
            u0 = *(const uint4*)(base);       // halves 0..7
            u1 = *(const uint4*)(base + 8);   // halves 8..15
        }
        *(uint4*)&As[arow * AS + ahalf * 16 + 0] = u0;
        *(uint4*)&As[arow * AS + ahalf * 16 + 8] = u1;

        // ---- W tile (32 x 128 fp32 -> fp16) ----
        {
            int kw = k0 + wk;
            const float* Wsrc; int kwl;
            if (KB == 0 || kw < KA) { Wsrc = Wl; kwl = kw; }
            else                    { Wsrc = Wr; kwl = kw - KA; }
#pragma unroll
            for (int j = 0; j < 4; j++) {
                float4 wv = *(const float4*)(Wsrc + (size_t)kwl * 128 + wn0 + j * 4);
                __half2 h0 = __floats2half2_rn(wv.x, wv.y);
                __half2 h1 = __floats2half2_rn(wv.z, wv.w);
                uint2 st;
                st.x = *(uint32_t*)&h0; st.y = *(uint32_t*)&h1;
                *(uint2*)&Ws[wk * WS + wn0 + j * 4] = st;
            }
        }
        __syncthreads();

        // ---- MMA: 2 k-chunks of 16 ----
#pragma unroll
        for (int kk = 0; kk < 2; kk++) {
            uint32_t af[4][4];
#pragma unroll
            for (int mt = 0; mt < 4; mt++) {
                int mrow = warpM * 64 + mt * 16 + (lane & 7) + ((lane >> 3) & 1) * 8;
                int mcol = kk * 16 + (lane >> 4) * 8;
                ldmatrix_x4(af[mt][0], af[mt][1], af[mt][2], af[mt][3],
                            smem_u32(&As[mrow * AS + mcol]));
            }
            uint32_t bf[4][2];
#pragma unroll
            for (int nt = 0; nt < 4; nt++) {
                int brow = kk * 16 + (lane & 7) + ((lane >> 3) & 1) * 8;
                int bcol = warpN * 32 + nt * 8;
                ldmatrix_x2t(bf[nt][0], bf[nt][1], smem_u32(&Ws[brow * WS + bcol]));
            }
#pragma unroll
            for (int mt = 0; mt < 4; mt++)
#pragma unroll
                for (int nt = 0; nt < 4; nt++)
                    mma_f16(acc[mt][nt], af[mt], bf[nt]);
        }
        __syncthreads();
    }

    // ---- epilogue: bias + relu -> fp16 ----
#pragma unroll
    for (int nt = 0; nt < 4; nt++) {
        int c = warpN * 32 + nt * 8 + (lane & 3) * 2;
        float b0 = bias[c], b1 = bias[c + 1];
#pragma unroll
        for (int mt = 0; mt < 4; mt++) {
            int r0 = row0 + warpM * 64 + mt * 16 + (lane >> 2);
            if (r0 < n) {
                __half2 v = __floats2half2_rn(fmaxf(acc[mt][nt][0] + b0, 0.f),
                                              fmaxf(acc[mt][nt][1] + b1, 0.f));
                *(__half2*)(out + (size_t)r0 * 128 + c) = v;
            }
            int r1 = r0 + 8;
            if (r1 < n) {
                __half2 v = __floats2half2_rn(fmaxf(acc[mt][nt][2] + b0, 0.f),
                                              fmaxf(acc[mt][nt][3] + b1, 0.f));
                *(__half2*)(out + (size_t)r1 * 128 + c) = v;
            }
        }
    }
}

// ---------------- fc head + aux layer1: warp per node -----------------------
__global__ void fc_a1_k(const __half* __restrict__ h2,
                        const float* __restrict__ Wfc, const float* __restrict__ bfc,
                        const float* __restrict__ Wa1, const float* __restrict__ ba1,
                        float* __restrict__ d13, __half* __restrict__ a1out, int n) {
    int gt = blockIdx.x * blockDim.x + threadIdx.x;
    int i = gt >> 5;
    int lane = gt & 31;
    if (i >= n) return;
    uint2 u = ((const uint2*)(h2 + (size_t)i * HH))[lane];
    float2 f0 = __half22float2(*(__half2*)&u.x);
    float2 f1 = __half22float2(*(__half2*)&u.y);
    int k = lane * 4;
    float s1 = f0.x * Wfc[(k + 0) * 3 + 0] + f0.y * Wfc[(k + 1) * 3 + 0]
             + f1.x * Wfc[(k + 2) * 3 + 0] + f1.y * Wfc[(k + 3) * 3 + 0];
    float s3 = f0.x * Wfc[(k + 0) * 3 + 2] + f0.y * Wfc[(k + 1) * 3 + 2]
             + f1.x * Wfc[(k + 2) * 3 + 2] + f1.y * Wfc[(k + 3) * 3 + 2];
#pragma unroll
    for (int off = 16; off > 0; off >>= 1) {
        s1 += __shfl_down_sync(0xffffffffu, s1, off);
        s3 += __shfl_down_sync(0xffffffffu, s3, off);
    }
    float d1 = __shfl_sync(0xffffffffu, s1, 0) + bfc[0];
    float d3 = __shfl_sync(0xffffffffu, s3, 0) + bfc[2];
    if (lane == 0) {
        d13[(size_t)i * 2 + 0] = d1;
        d13[(size_t)i * 2 + 1] = d3;
    }
    float4 w0 = *(const float4*)(Wa1 + k);
    float4 w1 = *(const float4*)(Wa1 + HH + k);
    float4 b  = *(const float4*)(ba1 + k);
    __half2 o0 = __floats2half2_rn(fmaxf(d1 * w0.x + d3 * w1.x + b.x, 0.f),
                                   fmaxf(d1 * w0.y + d3 * w1.y + b.y, 0.f));
    __half2 o1 = __floats2half2_rn(fmaxf(d1 * w0.z + d3 * w1.z + b.z, 0.f),
                                   fmaxf(d1 * w0.w + d3 * w1.w + b.w, 0.f));
    uint2 st;
    st.x = *(uint32_t*)&o0; st.y = *(uint32_t*)&o1;
    ((uint2*)(a1out + (size_t)i * HH))[lane] = st;
}

// ---------------- aux output + group accumulation: warp per node ------------
__global__ void final_k(const __half* __restrict__ a2,
                        const float* __restrict__ Wao, const float* __restrict__ bao,
                        const float* __restrict__ d13,
                        const int* __restrict__ batch,
                        float* __restrict__ g, int n) {
    __shared__ float sg[GG * 4];
    int tid = threadIdx.x;
    for (int j = tid; j < GG * 4; j += blockDim.x) sg[j] = 0.f;
    __syncthreads();

    int gt = blockIdx.x * blockDim.x + tid;
    int i = gt >> 5;
    int lane = gt & 31;
    if (i < n) {
        uint2 u = ((const uint2*)(a2 + (size_t)i * HH))[lane];
        float2 f0 = __half22float2(*(__half2*)&u.x);
        float2 f1 = __half22float2(*(__half2*)&u.y);
        float4 w = ((const float4*)Wao)[lane];
        float s = f0.x * w.x + f0.y * w.y + f1.x * w.z + f1.y * w.w;
#pragma unroll
        for (int off = 16; off > 0; off >>= 1)
            s += __shfl_down_sync(0xffffffffu, s, off);
        if (lane == 0) {
            float aux = s + bao[0];
            int b = batch[i];
            atomicAdd(&sg[b * 4 + 0], d13[(size_t)i * 2 + 0]);
            atomicAdd(&sg[b * 4 + 1], aux);
            atomicAdd(&sg[b * 4 + 2], d13[(size_t)i * 2 + 1]);
            atomicAdd(&sg[b * 4 + 3], 1.0f);
        }
    }
    __syncthreads();
    for (int j = tid; j < GG * 4; j += blockDim.x)
        if (sg[j] != 0.f) atomicAdd(&g[j], sg[j]);
}

// ---------------- finalize: group mean --------------------------------------
__global__ void finalize_k(const float* __restrict__ g, float* __restrict__ out) {
    int t = blockIdx.x * blockDim.x + threadIdx.x;
    if (t < GG * 3) {
        int grp = t / 3, c = t % 3;
        out[t] = g[grp * 4 + c] / fmaxf(g[grp * 4 + 3], 1.0f);
    }
}

// ---------------- launch -----------------------------------------------------
extern "C" void kernel_launch(void* const* d_in, const int* in_sizes, int n_in,
                              void* d_out, int out_size) {
    const float* x   = (const float*)d_in[0];
    const int*   ei  = (const int*)d_in[1];
    const int*   bat = (const int*)d_in[2];
    const float* Wl0 = (const float*)d_in[3];
    const float* bl0 = (const float*)d_in[4];
    const float* Wr0 = (const float*)d_in[5];
    const float* Wl1 = (const float*)d_in[6];
    const float* bl1 = (const float*)d_in[7];
    const float* Wr1 = (const float*)d_in[8];
    const float* Wl2 = (const float*)d_in[9];
    const float* bl2 = (const float*)d_in[10];
    const float* Wr2 = (const float*)d_in[11];
    const float* Wfc = (const float*)d_in[12];
    const float* bfc = (const float*)d_in[13];
    const float* Wa1 = (const float*)d_in[14];
    const float* ba1 = (const float*)d_in[15];
    const float* Wa2 = (const float*)d_in[16];
    const float* ba2 = (const float*)d_in[17];
    const float* Wao = (const float*)d_in[18];
    const float* bao = (const float*)d_in[19];
    float* out = (float*)d_out;

    int N = in_sizes[0] / EIN;
    int E = in_sizes[1] / 2;
    const int* src = ei;
    const int* dst = ei + E;

    void* p;
    cudaGetSymbolAddress(&p, d_M);      __half* M  = (__half*)p;
    cudaGetSymbolAddress(&p, d_HA);     __half* HA = (__half*)p;
    cudaGetSymbolAddress(&p, d_HB);     __half* HB = (__half*)p;
    cudaGetSymbolAddress(&p, d_xh);     __half* xh = (__half*)p;
    cudaGetSymbolAddress(&p, d_d13);    float* d13 = (float*)p;
    cudaGetSymbolAddress(&p, d_g);      float* g   = (float*)p;
    cudaGetSymbolAddress(&p, d_deg);    int* deg    = (int*)p;
    cudaGetSymbolAddress(&p, d_rowptr); int* rowptr = (int*)p;
    cudaGetSymbolAddress(&p, d_cursor); int* cursor = (int*)p;
    cudaGetSymbolAddress(&p, d_adj);    int* adj    = (int*)p;
    cudaGetSymbolAddress(&p, d_blksum); int* blksum = (int*)p;

    int nb = (N + 1023) / 1024;

    // --- CSR build + x conversion ---
    zero_deg_g<<<(N + 255) / 256, 256>>>(deg, g, N);
    cvt_x_k<<<1024, 256>>>((const float4*)x, (__half2*)xh, N * EIN / 4);
    hist_k<<<(E + 255) / 256, 256>>>(dst, deg, E);
    scan1_k<<<nb, 1024>>>(deg, rowptr, blksum, N);
    scan2_k<<<1, 128>>>(blksum, nb);
    scan3_k<<<(N + 1023) / 1024, 1024>>>(rowptr, blksum, cursor, N, E);
    fill_k<<<(E + 255) / 256, 256>>>(src, dst, cursor, adj, E);

    int wgrid = ((size_t)N * 32 + 255) / 256;
    int gblk = (N + 127) / 128;

    // --- layer 0 ---
    gather32h_k<<<wgrid, 256>>>(xh, rowptr, adj, M, N);
    sage_gemm_h<EIN, EIN><<<gblk, 256>>>(M, xh, Wl0, Wr0, bl0, HA, N);

    // --- layer 1 ---
    gather128h_k<<<wgrid, 256>>>(HA, rowptr, adj, M, N);
    sage_gemm_h<HH, HH><<<gblk, 256>>>(M, HA, Wl1, Wr1, bl1, HB, N);

    // --- layer 2 ---
    gather128h_k<<<wgrid, 256>>>(HB, rowptr, adj, M, N);
    sage_gemm_h<HH, HH><<<gblk, 256>>>(M, HB, Wl2, Wr2, bl2, HA, N);

    // --- heads ---
    fc_a1_k<<<wgrid, 256>>>(HA, Wfc, bfc, Wa1, ba1, d13, M, N);
    sage_gemm_h<HH, 0><<<gblk, 256>>>(M, nullptr, Wa2, nullptr, ba2, HB, N);
    final_k<<<wgrid, 256>>>(HB, Wao, bao, d13, bat, g, N);
    finalize_k<<<1, 256>>>(g, out);
}

// round 11
// speedup vs baseline: 3.3637x; 1.1057x over previous
#include <cuda_runtime.h>
#include <cuda_fp16.h>
#include <cstdint>

#define NN 100000
#define EE 1600000
#define HH 128
#define GG 64
#define EIN 32

// ---------------- static device scratch -------------------------------------
__device__ __align__(16) __half d_M[(size_t)NN * HH];    // mean scratch / a1
__device__ __align__(16) __half d_HA[(size_t)NN * HH];   // h0 / h2
__device__ __align__(16) __half d_HB[(size_t)NN * HH];   // h1 / a2
__device__ __align__(16) __half d_xh[(size_t)NN * EIN];  // x in fp16
__device__ __align__(16) __half d_Wh[90112];             // packed fp16 weights
__device__ __align__(16) float d_d13[(size_t)NN * 2];
__device__ __align__(16) float d_g[GG * 4];
__device__ int d_deg[NN];
__device__ int d_rowptr[NN + 1];
__device__ int d_cursor[NN];
__device__ int d_adj[EE];
__device__ int d_blksum[256];

// packed weight offsets (halves)
#define W0_OFF 0          // [Wl0;Wr0]  64 x 128
#define W1_OFF 8192       // [Wl1;Wr1] 256 x 128
#define W2_OFF 40960      // [Wl2;Wr2] 256 x 128
#define WA2_OFF 73728     // Wa2       128 x 128
#define WH_TOTAL 90112

// ---------------- CSR build + prep ------------------------------------------
__global__ void zero_deg_g(int* __restrict__ deg, float* __restrict__ g, int n) {
    int i = blockIdx.x * blockDim.x + threadIdx.x;
    if (i < n) deg[i] = 0;
    if (i < GG * 4) g[i] = 0.f;
}

__global__ void cvt_x_k(const float4* __restrict__ x4, __half2* __restrict__ xh2, int n4) {
    int stride = gridDim.x * blockDim.x;
    for (int i = blockIdx.x * blockDim.x + threadIdx.x; i < n4; i += stride) {
        float4 v = x4[i];
        xh2[i * 2 + 0] = __floats2half2_rn(v.x, v.y);
        xh2[i * 2 + 1] = __floats2half2_rn(v.z, v.w);
    }
}

__global__ void prep_w_k(const float* __restrict__ Wl0, const float* __restrict__ Wr0,
                         const float* __restrict__ Wl1, const float* __restrict__ Wr1,
                         const float* __restrict__ Wl2, const float* __restrict__ Wr2,
                         const float* __restrict__ Wa2, __half* __restrict__ Wh) {
    int i = blockIdx.x * blockDim.x + threadIdx.x;
    if (i >= WH_TOTAL) return;
    float v;
    if (i < W1_OFF) {                 // [Wl0;Wr0] 64x128
        int r = i >> 7, c = i & 127;
        v = (r < 32) ? Wl0[r * 128 + c] : Wr0[(r - 32) * 128 + c];
    } else if (i < W2_OFF) {          // [Wl1;Wr1] 256x128
        int j = i - W1_OFF;
        int r = j >> 7, c = j & 127;
        v = (r < 128) ? Wl1[r * 128 + c] : Wr1[(r - 128) * 128 + c];
    } else if (i < WA2_OFF) {         // [Wl2;Wr2] 256x128
        int j = i - W2_OFF;
        int r = j >> 7, c = j & 127;
        v = (r < 128) ? Wl2[r * 128 + c] : Wr2[(r - 128) * 128 + c];
    } else {                          // Wa2 128x128
        v = Wa2[i - WA2_OFF];
    }
    Wh[i] = __float2half_rn(v);
}

__global__ void hist_k(const int* __restrict__ dst, int* __restrict__ deg, int E) {
    int e = blockIdx.x * blockDim.x + threadIdx.x;
    if (e < E) atomicAdd(&deg[dst[e]], 1);
}

__global__ void scan1_k(const int* __restrict__ deg, int* __restrict__ excl,
                        int* __restrict__ blksum, int n) {
    __shared__ int sh[1024];
    int tid = threadIdx.x;
    int i = blockIdx.x * 1024 + tid;
    int v = (i < n) ? deg[i] : 0;
    sh[tid] = v;
    __syncthreads();
#pragma unroll
    for (int off = 1; off < 1024; off <<= 1) {
        int t = (tid >= off) ? sh[tid - off] : 0;
        __syncthreads();
        sh[tid] += t;
        __syncthreads();
    }
    if (i < n) excl[i] = sh[tid] - v;
    if (tid == 1023) blksum[blockIdx.x] = sh[1023];
}

__global__ void scan2_k(int* __restrict__ blksum, int nb) {
    __shared__ int sh[128];
    int tid = threadIdx.x;
    int v = (tid < nb) ? blksum[tid] : 0;
    sh[tid] = v;
    __syncthreads();
#pragma unroll
    for (int off = 1; off < 128; off <<= 1) {
        int t = (tid >= off) ? sh[tid - off] : 0;
        __syncthreads();
        sh[tid] += t;
        __syncthreads();
    }
    if (tid < nb) blksum[tid] = sh[tid] - v;
}

__global__ void scan3_k(int* __restrict__ rowptr, const int* __restrict__ blksum,
                        int* __restrict__ cursor, int n, int E) {
    int i = blockIdx.x * blockDim.x + threadIdx.x;
    if (i < n) {
        int r = rowptr[i] + blksum[i >> 10];
        rowptr[i] = r;
        cursor[i] = r;
    }
    if (i == 0) rowptr[n] = E;
}

__global__ void fill_k(const int* __restrict__ src, const int* __restrict__ dst,
                       int* __restrict__ cursor, int* __restrict__ adj, int E) {
    int e = blockIdx.x * blockDim.x + threadIdx.x;
    if (e < E) {
        int slot = atomicAdd(&cursor[dst[e]], 1);
        adj[slot] = src[e];
    }
}

// ---------------- mean gather: 32-dim fp16, warp per node -------------------
__global__ void gather32h_k(const __half* __restrict__ xh,
                            const int* __restrict__ rowptr, const int* __restrict__ adj,
                            __half* __restrict__ out, int n) {
    int gt = blockIdx.x * blockDim.x + threadIdx.x;
    int i = gt >> 5;
    int lane = gt & 31;
    if (i >= n) return;
    int b = rowptr[i], e = rowptr[i + 1];
    float acc = 0.f;
    int j = b;
    for (; j + 3 < e; j += 4) {
        int s0 = adj[j], s1 = adj[j + 1], s2 = adj[j + 2], s3 = adj[j + 3];
        acc += __half2float(xh[(size_t)s0 * EIN + lane])
             + __half2float(xh[(size_t)s1 * EIN + lane])
             + __half2float(xh[(size_t)s2 * EIN + lane])
             + __half2float(xh[(size_t)s3 * EIN + lane]);
    }
    for (; j < e; j++)
        acc += __half2float(xh[(size_t)adj[j] * EIN + lane]);
    float inv = 1.0f / (float)max(e - b, 1);
    out[(size_t)i * EIN + lane] = __float2half_rn(acc * inv);
}

// ---------------- mean gather: 128-dim fp16, warp per node ------------------
__global__ void gather128h_k(const __half* __restrict__ h,
                             const int* __restrict__ rowptr, const int* __restrict__ adj,
                             __half* __restrict__ out, int n) {
    int gt = blockIdx.x * blockDim.x + threadIdx.x;
    int i = gt >> 5;
    int lane = gt & 31;
    if (i >= n) return;
    int b = rowptr[i], e = rowptr[i + 1];
    float ax = 0.f, ay = 0.f, az = 0.f, aw = 0.f;
    int j = b;
    for (; j + 3 < e; j += 4) {
#pragma unroll
        for (int u = 0; u < 4; u++) {
            int s = adj[j + u];
            uint2 v = ((const uint2*)(h + (size_t)s * HH))[lane];
            float2 f0 = __half22float2(*(__half2*)&v.x);
            float2 f1 = __half22float2(*(__half2*)&v.y);
            ax += f0.x; ay += f0.y; az += f1.x; aw += f1.y;
        }
    }
    for (; j < e; j++) {
        int s = adj[j];
        uint2 v = ((const uint2*)(h + (size_t)s * HH))[lane];
        float2 f0 = __half22float2(*(__half2*)&v.x);
        float2 f1 = __half22float2(*(__half2*)&v.y);
        ax += f0.x; ay += f0.y; az += f1.x; aw += f1.y;
    }
    float inv = 1.0f / (float)max(e - b, 1);
    __half2 o0 = __floats2half2_rn(ax * inv, ay * inv);
    __half2 o1 = __floats2half2_rn(az * inv, aw * inv);
    uint2 st;
    st.x = *(uint32_t*)&o0; st.y = *(uint32_t*)&o1;
    ((uint2*)(out + (size_t)i * HH))[lane] = st;
}

// ---------------- fp16 MMA helpers ------------------------------------------
__device__ __forceinline__ uint32_t smem_u32(const void* p) {
    return (uint32_t)__cvta_generic_to_shared(p);
}
__device__ __forceinline__ void cp16(uint32_t daddr, const void* g, int srcsize) {
    asm volatile("cp.async.cg.shared.global [%0], [%1], 16, %2;"
                 :: "r"(daddr), "l"(g), "r"(srcsize));
}
__device__ __forceinline__ void cp_commit() {
    asm volatile("cp.async.commit_group;");
}
__device__ __forceinline__ void cp_wait0() {
    asm volatile("cp.async.wait_group 0;");
}
__device__ __forceinline__ void ldmatrix_x4(uint32_t& r0, uint32_t& r1,
                                            uint32_t& r2, uint32_t& r3, uint32_t addr) {
    asm volatile("ldmatrix.sync.aligned.m8n8.x4.shared.b16 {%0,%1,%2,%3}, [%4];"
                 : "=r"(r0), "=r"(r1), "=r"(r2), "=r"(r3) : "r"(addr));
}
__device__ __forceinline__ void ldmatrix_x2t(uint32_t& r0, uint32_t& r1, uint32_t addr) {
    asm volatile("ldmatrix.sync.aligned.m8n8.x2.trans.shared.b16 {%0,%1}, [%2];"
                 : "=r"(r0), "=r"(r1) : "r"(addr));
}
__device__ __forceinline__ void mma_f16(float* d, const uint32_t* a, const uint32_t* b) {
    asm volatile(
        "mma.sync.aligned.m16n8k16.row.col.f32.f16.f16.f32 "
        "{%0,%1,%2,%3}, {%4,%5,%6,%7}, {%8,%9}, {%0,%1,%2,%3};"
        : "+f"(d[0]), "+f"(d[1]), "+f"(d[2]), "+f"(d[3])
        : "r"(a[0]), "r"(a[1]), "r"(a[2]), "r"(a[3]), "r"(b[0]), "r"(b[1]));
}

// ---------------- fp16 tensor-core SAGE GEMM (double-buffered) --------------
// out[M,128](fp16) = relu([Aagg | Ax](fp16) @ Wh + bias), Wh packed K x 128 fp16
// BM=128 BN=128 BK=32, 8 warps, warp tile 64x32, m16n8k16, 2-stage cp.async.
#define AS 40    // As row stride (halves) = 80B (16B-aligned)
#define WS 136   // Ws row stride (halves) = 272B (16B-aligned)

template <int KA, int KB>
__global__ void __launch_bounds__(256)
sage_gemm_h(const __half* __restrict__ Aagg, const __half* __restrict__ Ax,
            const __half* __restrict__ Wh,
            const float* __restrict__ bias, __half* __restrict__ out, int n) {
    constexpr int K = KA + KB;
    constexpr int ITERS = K / 32;
    __shared__ __half As[2][128 * AS];
    __shared__ __half Ws[2][32 * WS];

    int tid = threadIdx.x;
    int lane = tid & 31;
    int wid = tid >> 5;
    int warpM = wid >> 2;     // 0..1 -> m*64
    int warpN = wid & 3;      // 0..3 -> n*32
    int row0 = blockIdx.x * 128;

    int arow = tid >> 1;
    int ahalf = tid & 1;      // which 16-half chunk of the 32-half row
    int grow = row0 + arow;
    bool rvalid = grow < n;
    int asz = rvalid ? 16 : 0;

    int wk = tid >> 3;        // 0..31
    int wn0 = (tid & 7) * 16;

    float acc[4][4][4];
#pragma unroll
    for (int mt = 0; mt < 4; mt++)
#pragma unroll
        for (int nt = 0; nt < 4; nt++)
#pragma unroll
            for (int q = 0; q < 4; q++) acc[mt][nt][q] = 0.f;

    auto issue_tile = [&](int k0, int s) {
        // A tile (128 x 32): 2 x 16B cp.async per thread
        const __half* Asrc; int kloc, astr;
        if (KB == 0 || k0 < KA) { Asrc = Aagg; kloc = k0; astr = KA; }
        else                    { Asrc = Ax; kloc = k0 - KA; astr = KB; }
        const __half* abase = Asrc + (size_t)grow * astr + kloc + ahalf * 16;
        uint32_t da = smem_u32(&As[s][arow * AS + ahalf * 16]);
        cp16(da, abase, asz);
        cp16(da + 16, abase + 8, asz);
        // W tile (32 x 128): 2 x 16B cp.async per thread
        const __half* wbase = Wh + (size_t)(k0 + wk) * 128 + wn0;
        uint32_t dw = smem_u32(&Ws[s][wk * WS + wn0]);
        cp16(dw, wbase, 16);
        cp16(dw + 16, wbase + 8, 16);
    };

    issue_tile(0, 0);
    cp_commit();

#pragma unroll
    for (int it = 0; it < ITERS; it++) {
        int s = it & 1;
        cp_wait0();
        __syncthreads();
        if (it + 1 < ITERS) {
            issue_tile((it + 1) * 32, s ^ 1);
            cp_commit();
        }
        // ---- MMA on stage s: 2 k-chunks of 16 ----
#pragma unroll
        for (int kk = 0; kk < 2; kk++) {
            uint32_t af[4][4];
#pragma unroll
            for (int mt = 0; mt < 4; mt++) {
                int mrow = warpM * 64 + mt * 16 + (lane & 7) + ((lane >> 3) & 1) * 8;
                int mcol = kk * 16 + (lane >> 4) * 8;
                ldmatrix_x4(af[mt][0], af[mt][1], af[mt][2], af[mt][3],
                            smem_u32(&As[s][mrow * AS + mcol]));
            }
            uint32_t bf[4][2];
#pragma unroll
            for (int nt = 0; nt < 4; nt++) {
                int brow = kk * 16 + (lane & 7) + ((lane >> 3) & 1) * 8;
                int bcol = warpN * 32 + nt * 8;
                ldmatrix_x2t(bf[nt][0], bf[nt][1], smem_u32(&Ws[s][brow * WS + bcol]));
            }
#pragma unroll
            for (int mt = 0; mt < 4; mt++)
#pragma unroll
                for (int nt = 0; nt < 4; nt++)
                    mma_f16(acc[mt][nt], af[mt], bf[nt]);
        }
    }

    // ---- epilogue: bias + relu -> fp16 ----
#pragma unroll
    for (int nt = 0; nt < 4; nt++) {
        int c = warpN * 32 + nt * 8 + (lane & 3) * 2;
        float b0 = bias[c], b1 = bias[c + 1];
#pragma unroll
        for (int mt = 0; mt < 4; mt++) {
            int r0 = row0 + warpM * 64 + mt * 16 + (lane >> 2);
            if (r0 < n) {
                __half2 v = __floats2half2_rn(fmaxf(acc[mt][nt][0] + b0, 0.f),
                                              fmaxf(acc[mt][nt][1] + b1, 0.f));
                *(__half2*)(out + (size_t)r0 * 128 + c) = v;
            }
            int r1 = r0 + 8;
            if (r1 < n) {
                __half2 v = __floats2half2_rn(fmaxf(acc[mt][nt][2] + b0, 0.f),
                                              fmaxf(acc[mt][nt][3] + b1, 0.f));
                *(__half2*)(out + (size_t)r1 * 128 + c) = v;
            }
        }
    }
}

// ---------------- fc head + aux layer1: warp per node -----------------------
__global__ void fc_a1_k(const __half* __restrict__ h2,
                        const float* __restrict__ Wfc, const float* __restrict__ bfc,
                        const float* __restrict__ Wa1, const float* __restrict__ ba1,
                        float* __restrict__ d13, __half* __restrict__ a1out, int n) {
    int gt = blockIdx.x * blockDim.x + threadIdx.x;
    int i = gt >> 5;
    int lane = gt & 31;
    if (i >= n) return;
    uint2 u = ((const uint2*)(h2 + (size_t)i * HH))[lane];
    float2 f0 = __half22float2(*(__half2*)&u.x);
    float2 f1 = __half22float2(*(__half2*)&u.y);
    int k = lane * 4;
    float s1 = f0.x * Wfc[(k + 0) * 3 + 0] + f0.y * Wfc[(k + 1) * 3 + 0]
             + f1.x * Wfc[(k + 2) * 3 + 0] + f1.y * Wfc[(k + 3) * 3 + 0];
    float s3 = f0.x * Wfc[(k + 0) * 3 + 2] + f0.y * Wfc[(k + 1) * 3 + 2]
             + f1.x * Wfc[(k + 2) * 3 + 2] + f1.y * Wfc[(k + 3) * 3 + 2];
#pragma unroll
    for (int off = 16; off > 0; off >>= 1) {
        s1 += __shfl_down_sync(0xffffffffu, s1, off);
        s3 += __shfl_down_sync(0xffffffffu, s3, off);
    }
    float d1 = __shfl_sync(0xffffffffu, s1, 0) + bfc[0];
    float d3 = __shfl_sync(0xffffffffu, s3, 0) + bfc[2];
    if (lane == 0) {
        d13[(size_t)i * 2 + 0] = d1;
        d13[(size_t)i * 2 + 1] = d3;
    }
    float4 w0 = *(const float4*)(Wa1 + k);
    float4 w1 = *(const float4*)(Wa1 + HH + k);
    float4 b  = *(const float4*)(ba1 + k);
    __half2 o0 = __floats2half2_rn(fmaxf(d1 * w0.x + d3 * w1.x + b.x, 0.f),
                                   fmaxf(d1 * w0.y + d3 * w1.y + b.y, 0.f));
    __half2 o1 = __floats2half2_rn(fmaxf(d1 * w0.z + d3 * w1.z + b.z, 0.f),
                                   fmaxf(d1 * w0.w + d3 * w1.w + b.w, 0.f));
    uint2 st;
    st.x = *(uint32_t*)&o0; st.y = *(uint32_t*)&o1;
    ((uint2*)(a1out + (size_t)i * HH))[lane] = st;
}

// ---------------- aux output + group accumulation: warp per node ------------
__global__ void final_k(const __half* __restrict__ a2,
                        const float* __restrict__ Wao, const float* __restrict__ bao,
                        const float* __restrict__ d13,
                        const int* __restrict__ batch,
                        float* __restrict__ g, int n) {
    __shared__ float sg[GG * 4];
    int tid = threadIdx.x;
    for (int j = tid; j < GG * 4; j += blockDim.x) sg[j] = 0.f;
    __syncthreads();

    int gt = blockIdx.x * blockDim.x + tid;
    int i = gt >> 5;
    int lane = gt & 31;
    if (i < n) {
        uint2 u = ((const uint2*)(a2 + (size_t)i * HH))[lane];
        float2 f0 = __half22float2(*(__half2*)&u.x);
        float2 f1 = __half22float2(*(__half2*)&u.y);
        float4 w = ((const float4*)Wao)[lane];
        float s = f0.x * w.x + f0.y * w.y + f1.x * w.z + f1.y * w.w;
#pragma unroll
        for (int off = 16; off > 0; off >>= 1)
            s += __shfl_down_sync(0xffffffffu, s, off);
        if (lane == 0) {
            float aux = s + bao[0];
            int b = batch[i];
            atomicAdd(&sg[b * 4 + 0], d13[(size_t)i * 2 + 0]);
            atomicAdd(&sg[b * 4 + 1], aux);
            atomicAdd(&sg[b * 4 + 2], d13[(size_t)i * 2 + 1]);
            atomicAdd(&sg[b * 4 + 3], 1.0f);
        }
    }
    __syncthreads();
    for (int j = tid; j < GG * 4; j += blockDim.x)
        if (sg[j] != 0.f) atomicAdd(&g[j], sg[j]);
}

// ---------------- finalize: group mean --------------------------------------
__global__ void finalize_k(const float* __restrict__ g, float* __restrict__ out) {
    int t = blockIdx.x * blockDim.x + threadIdx.x;
    if (t < GG * 3) {
        int grp = t / 3, c = t % 3;
        out[t] = g[grp * 4 + c] / fmaxf(g[grp * 4 + 3], 1.0f);
    }
}

// ---------------- launch -----------------------------------------------------
extern "C" void kernel_launch(void* const* d_in, const int* in_sizes, int n_in,
                              void* d_out, int out_size) {
    const float* x   = (const float*)d_in[0];
    const int*   ei  = (const int*)d_in[1];
    const int*   bat = (const int*)d_in[2];
    const float* Wl0 = (const float*)d_in[3];
    const float* bl0 = (const float*)d_in[4];
    const float* Wr0 = (const float*)d_in[5];
    const float* Wl1 = (const float*)d_in[6];
    const float* bl1 = (const float*)d_in[7];
    const float* Wr1 = (const float*)d_in[8];
    const float* Wl2 = (const float*)d_in[9];
    const float* bl2 = (const float*)d_in[10];
    const float* Wr2 = (const float*)d_in[11];
    const float* Wfc = (const float*)d_in[12];
    const float* bfc = (const float*)d_in[13];
    const float* Wa1 = (const float*)d_in[14];
    const float* ba1 = (const float*)d_in[15];
    const float* Wa2 = (const float*)d_in[16];
    const float* ba2 = (const float*)d_in[17];
    const float* Wao = (const float*)d_in[18];
    const float* bao = (const float*)d_in[19];
    float* out = (float*)d_out;

    int N = in_sizes[0] / EIN;
    int E = in_sizes[1] / 2;
    const int* src = ei;
    const int* dst = ei + E;

    void* p;
    cudaGetSymbolAddress(&p, d_M);      __half* M  = (__half*)p;
    cudaGetSymbolAddress(&p, d_HA);     __half* HA = (__half*)p;
    cudaGetSymbolAddress(&p, d_HB);     __half* HB = (__half*)p;
    cudaGetSymbolAddress(&p, d_xh);     __half* xh = (__half*)p;
    cudaGetSymbolAddress(&p, d_Wh);     __half* Wh = (__half*)p;
    cudaGetSymbolAddress(&p, d_d13);    float* d13 = (float*)p;
    cudaGetSymbolAddress(&p, d_g);      float* g   = (float*)p;
    cudaGetSymbolAddress(&p, d_deg);    int* deg    = (int*)p;
    cudaGetSymbolAddress(&p, d_rowptr); int* rowptr = (int*)p;
    cudaGetSymbolAddress(&p, d_cursor); int* cursor = (int*)p;
    cudaGetSymbolAddress(&p, d_adj);    int* adj    = (int*)p;
    cudaGetSymbolAddress(&p, d_blksum); int* blksum = (int*)p;

    int nb = (N + 1023) / 1024;

    // --- prep: CSR build + fp16 conversions ---
    zero_deg_g<<<(N + 255) / 256, 256>>>(deg, g, N);
    cvt_x_k<<<1024, 256>>>((const float4*)x, (__half2*)xh, N * EIN / 4);
    prep_w_k<<<(WH_TOTAL + 255) / 256, 256>>>(Wl0, Wr0, Wl1, Wr1, Wl2, Wr2, Wa2, Wh);
    hist_k<<<(E + 255) / 256, 256>>>(dst, deg, E);
    scan1_k<<<nb, 1024>>>(deg, rowptr, blksum, N);
    scan2_k<<<1, 128>>>(blksum, nb);
    scan3_k<<<(N + 1023) / 1024, 1024>>>(rowptr, blksum, cursor, N, E);
    fill_k<<<(E + 255) / 256, 256>>>(src, dst, cursor, adj, E);

    int wgrid = ((size_t)N * 32 + 255) / 256;
    int gblk = (N + 127) / 128;

    // --- layer 0 ---
    gather32h_k<<<wgrid, 256>>>(xh, rowptr, adj, M, N);
    sage_gemm_h<EIN, EIN><<<gblk, 256>>>(M, xh, Wh + W0_OFF, bl0, HA, N);

    // --- layer 1 ---
    gather128h_k<<<wgrid, 256>>>(HA, rowptr, adj, M, N);
    sage_gemm_h<HH, HH><<<gblk, 256>>>(M, HA, Wh + W1_OFF, bl1, HB, N);

    // --- layer 2 ---
    gather128h_k<<<wgrid, 256>>>(HB, rowptr, adj, M, N);
    sage_gemm_h<HH, HH><<<gblk, 256>>>(M, HB, Wh + W2_OFF, bl2, HA, N);

    // --- heads ---
    fc_a1_k<<<wgrid, 256>>>(HA, Wfc, bfc, Wa1, ba1, d13, M, N);
    sage_gemm_h<HH, 0><<<gblk, 256>>>(M, nullptr, Wh + WA2_OFF, ba2, HB, N);
    final_k<<<wgrid, 256>>>(HB, Wao, bao, d13, bat, g, N);
    finalize_k<<<1, 256>>>(g, out);
}